// round 3
// baseline (speedup 1.0000x reference)
#include <cuda_runtime.h>
#include <cstdint>

// Problem constants (fixed-shape variant)
#define BS 4
#define NQ 10000
#define NH 8
#define HD 32
#define NP 4
#define SH 100
#define SW 100

// value layout: [b][pix][h][d], pix = y*SW + x
// loc layout:   [b][q][h][0][p][2]  -> ((warp)*NP + p)*2
// aw layout:    [b][q][h][0][p]     -> warp*NP + p
// out layout:   [b][q][h*HD + d]    -> warp*HD + lane
// with warp = (b*NQ + q)*NH + h

__global__ __launch_bounds__(256) void deform_attn_kernel(
    const float* __restrict__ value,
    const float* __restrict__ loc,
    const float* __restrict__ aw,
    float* __restrict__ out)
{
    const int gtid = blockIdx.x * blockDim.x + threadIdx.x;
    const int warp = gtid >> 5;
    const int lane = gtid & 31;
    if (warp >= BS * NQ * NH) return;

    const int h = warp & (NH - 1);
    const int b = warp / (NQ * NH);

    // base pointer for this (b, h, lane): add pix*NH*HD to index pixels
    const float* vbase = value + (size_t)b * (SH * SW * NH * HD) + h * HD + lane;
    const float2* lptr = reinterpret_cast<const float2*>(loc) + (size_t)warp * NP;
    const float* wptr = aw + (size_t)warp * NP;

    float acc = 0.0f;

#pragma unroll
    for (int p = 0; p < NP; ++p) {
        const float2 l = __ldg(lptr + p);
        const float w = __ldg(wptr + p);

        // grid = 2*loc - 1; unnormalize align_corners=False:
        // x = (grid_x + 1) * W/2 - 0.5  ==  loc_x * W - 0.5
        const float x = l.x * (float)SW - 0.5f;
        const float y = l.y * (float)SH - 0.5f;

        const float xf = floorf(x);
        const float yf = floorf(y);
        const int x0 = (int)xf;
        const int y0 = (int)yf;
        const float tx = x - xf;
        const float ty = y - yf;

        const float w00 = (1.0f - tx) * (1.0f - ty) * w;
        const float w10 = tx * (1.0f - ty) * w;
        const float w01 = (1.0f - tx) * ty * w;
        const float w11 = tx * ty * w;

        const bool vx0 = (x0 >= 0) && (x0 < SW);
        const bool vx1 = (x0 + 1 >= 0) && (x0 + 1 < SW);
        const bool vy0 = (y0 >= 0) && (y0 < SH);
        const bool vy1 = (y0 + 1 >= 0) && (y0 + 1 < SH);

        const int pixstride = NH * HD;  // 256 floats between adjacent pixels

        if (vy0) {
            const float* row = vbase + (size_t)y0 * SW * pixstride;
            if (vx0) acc += w00 * __ldg(row + (size_t)x0 * pixstride);
            if (vx1) acc += w10 * __ldg(row + (size_t)(x0 + 1) * pixstride);
        }
        if (vy1) {
            const float* row = vbase + (size_t)(y0 + 1) * SW * pixstride;
            if (vx0) acc += w01 * __ldg(row + (size_t)x0 * pixstride);
            if (vx1) acc += w11 * __ldg(row + (size_t)(x0 + 1) * pixstride);
        }
    }

    out[(size_t)warp * HD + lane] = acc;
}

extern "C" void kernel_launch(void* const* d_in, const int* in_sizes, int n_in,
                              void* d_out, int out_size)
{
    const float* value = (const float*)d_in[0];
    // d_in[1] = value_spatial_shapes (int64), unused in fixed-size variant
    const float* loc = (const float*)d_in[2];
    const float* aw = (const float*)d_in[3];
    float* out = (float*)d_out;

    const int total_warps = BS * NQ * NH;            // 320000
    const int threads = 256;                          // 8 warps per block
    const int blocks = (total_warps * 32 + threads - 1) / threads;  // 40000

    deform_attn_kernel<<<blocks, threads>>>(value, loc, aw, out);
}

// round 4
// speedup vs baseline: 1.0012x; 1.0012x over previous
#include <cuda_runtime.h>
#include <cstdint>

// Problem constants (fixed-shape variant)
#define BS 4
#define NQ 10000
#define NH 8
#define HD 32
#define NP 4
#define SH 100
#define SW 100

// value layout: [b][pix][h][d], pix = y*SW + x
// loc layout:   [b][q][h][0][p][2]  -> ((warp)*NP + p)*2
// aw layout:    [b][q][h][0][p]     -> warp*NP + p
// out layout:   [b][q][h*HD + d]    -> warp*HD + lane
// with warp = (b*NQ + q)*NH + h

__global__ __launch_bounds__(256) void deform_attn_kernel(
    const float* __restrict__ value,
    const float* __restrict__ loc,
    const float* __restrict__ aw,
    float* __restrict__ out)
{
    const int gtid = blockIdx.x * blockDim.x + threadIdx.x;
    const int warp = gtid >> 5;
    const int lane = gtid & 31;
    if (warp >= BS * NQ * NH) return;

    const int h = warp & (NH - 1);
    const int b = warp / (NQ * NH);

    // base pointer for this (b, h, lane): add pix*NH*HD to index pixels
    const float* vbase = value + (size_t)b * (SH * SW * NH * HD) + h * HD + lane;
    const float2* lptr = reinterpret_cast<const float2*>(loc) + (size_t)warp * NP;
    const float* wptr = aw + (size_t)warp * NP;

    float acc = 0.0f;

#pragma unroll
    for (int p = 0; p < NP; ++p) {
        const float2 l = __ldg(lptr + p);
        const float w = __ldg(wptr + p);

        // grid = 2*loc - 1; unnormalize align_corners=False:
        // x = (grid_x + 1) * W/2 - 0.5  ==  loc_x * W - 0.5
        const float x = l.x * (float)SW - 0.5f;
        const float y = l.y * (float)SH - 0.5f;

        const float xf = floorf(x);
        const float yf = floorf(y);
        const int x0 = (int)xf;
        const int y0 = (int)yf;
        const float tx = x - xf;
        const float ty = y - yf;

        const float w00 = (1.0f - tx) * (1.0f - ty) * w;
        const float w10 = tx * (1.0f - ty) * w;
        const float w01 = (1.0f - tx) * ty * w;
        const float w11 = tx * ty * w;

        const bool vx0 = (x0 >= 0) && (x0 < SW);
        const bool vx1 = (x0 + 1 >= 0) && (x0 + 1 < SW);
        const bool vy0 = (y0 >= 0) && (y0 < SH);
        const bool vy1 = (y0 + 1 >= 0) && (y0 + 1 < SH);

        const int pixstride = NH * HD;  // 256 floats between adjacent pixels

        if (vy0) {
            const float* row = vbase + (size_t)y0 * SW * pixstride;
            if (vx0) acc += w00 * __ldg(row + (size_t)x0 * pixstride);
            if (vx1) acc += w10 * __ldg(row + (size_t)(x0 + 1) * pixstride);
        }
        if (vy1) {
            const float* row = vbase + (size_t)(y0 + 1) * SW * pixstride;
            if (vx0) acc += w01 * __ldg(row + (size_t)x0 * pixstride);
            if (vx1) acc += w11 * __ldg(row + (size_t)(x0 + 1) * pixstride);
        }
    }

    out[(size_t)warp * HD + lane] = acc;
}

extern "C" void kernel_launch(void* const* d_in, const int* in_sizes, int n_in,
                              void* d_out, int out_size)
{
    const float* value = (const float*)d_in[0];
    // d_in[1] = value_spatial_shapes (int64), unused in fixed-size variant
    const float* loc = (const float*)d_in[2];
    const float* aw = (const float*)d_in[3];
    float* out = (float*)d_out;

    const int total_warps = BS * NQ * NH;            // 320000
    const int threads = 256;                          // 8 warps per block
    const int blocks = (total_warps * 32 + threads - 1) / threads;  // 40000

    deform_attn_kernel<<<blocks, threads>>>(value, loc, aw, out);
}

// round 5
// speedup vs baseline: 1.0114x; 1.0102x over previous
#include <cuda_runtime.h>
#include <cstdint>

// Problem constants (fixed-shape variant)
#define BS 4
#define NQ 10000
#define NH 8
#define HD 32
#define NP 4
#define SH 100
#define SW 100

// value layout: [b][pix][h][d], pix = y*SW + x
// loc layout:   [b][q][h][0][p][2]  -> ((warp)*NP + p)*2
// aw layout:    [b][q][h][0][p]     -> warp*NP + p
// out layout:   [b][q][h*HD + d]    -> warp*HD + lane
// with warp = (b*NQ + q)*NH + h

__global__ __launch_bounds__(256) void deform_attn_kernel(
    const float* __restrict__ value,
    const float* __restrict__ loc,
    const float* __restrict__ aw,
    float* __restrict__ out)
{
    const int gtid = blockIdx.x * blockDim.x + threadIdx.x;
    const int warp = gtid >> 5;
    const int lane = gtid & 31;
    if (warp >= BS * NQ * NH) return;

    const int h = warp & (NH - 1);
    const int b = warp / (NQ * NH);

    // base pointer for this (b, h, lane): add pix*NH*HD to index pixels
    const float* vbase = value + (size_t)b * (SH * SW * NH * HD) + h * HD + lane;
    const float2* lptr = reinterpret_cast<const float2*>(loc) + (size_t)warp * NP;
    const float* wptr = aw + (size_t)warp * NP;

    float acc = 0.0f;

#pragma unroll
    for (int p = 0; p < NP; ++p) {
        const float2 l = __ldg(lptr + p);
        const float w = __ldg(wptr + p);

        // grid = 2*loc - 1; unnormalize align_corners=False:
        // x = (grid_x + 1) * W/2 - 0.5  ==  loc_x * W - 0.5
        const float x = l.x * (float)SW - 0.5f;
        const float y = l.y * (float)SH - 0.5f;

        const float xf = floorf(x);
        const float yf = floorf(y);
        const int x0 = (int)xf;
        const int y0 = (int)yf;
        const float tx = x - xf;
        const float ty = y - yf;

        const float w00 = (1.0f - tx) * (1.0f - ty) * w;
        const float w10 = tx * (1.0f - ty) * w;
        const float w01 = (1.0f - tx) * ty * w;
        const float w11 = tx * ty * w;

        const bool vx0 = (x0 >= 0) && (x0 < SW);
        const bool vx1 = (x0 + 1 >= 0) && (x0 + 1 < SW);
        const bool vy0 = (y0 >= 0) && (y0 < SH);
        const bool vy1 = (y0 + 1 >= 0) && (y0 + 1 < SH);

        const int pixstride = NH * HD;  // 256 floats between adjacent pixels

        if (vy0) {
            const float* row = vbase + (size_t)y0 * SW * pixstride;
            if (vx0) acc += w00 * __ldg(row + (size_t)x0 * pixstride);
            if (vx1) acc += w10 * __ldg(row + (size_t)(x0 + 1) * pixstride);
        }
        if (vy1) {
            const float* row = vbase + (size_t)(y0 + 1) * SW * pixstride;
            if (vx0) acc += w01 * __ldg(row + (size_t)x0 * pixstride);
            if (vx1) acc += w11 * __ldg(row + (size_t)(x0 + 1) * pixstride);
        }
    }

    out[(size_t)warp * HD + lane] = acc;
}

extern "C" void kernel_launch(void* const* d_in, const int* in_sizes, int n_in,
                              void* d_out, int out_size)
{
    const float* value = (const float*)d_in[0];
    // d_in[1] = value_spatial_shapes (int64), unused in fixed-size variant
    const float* loc = (const float*)d_in[2];
    const float* aw = (const float*)d_in[3];
    float* out = (float*)d_out;

    const int total_warps = BS * NQ * NH;            // 320000
    const int threads = 256;                          // 8 warps per block
    const int blocks = (total_warps * 32 + threads - 1) / threads;  // 40000

    deform_attn_kernel<<<blocks, threads>>>(value, loc, aw, out);
}

// round 6
// speedup vs baseline: 2.3142x; 2.2882x over previous
#include <cuda_runtime.h>
#include <cstdint>

// Problem constants (fixed-shape variant)
#define BS 4
#define NQ 10000
#define NH 8
#define HD 32
#define NP 4
#define SH 100
#define SW 100

// value layout: [b][pix][h][d], pix = y*SW + x   (pixel stride = NH*HD = 256 floats = 64 float4)
// loc layout:   [b][q][h][0][p][2]
// aw layout:    [b][q][h][0][p]
// out layout:   [b][q][h*HD + d]
//
// One warp handles (b, q, head-group hg) where hg selects 4 heads.
// lane: g = lane>>3 -> head = hg*4+g ; sub = lane&7 -> channels [sub*4, sub*4+4)
// Each corner gather per 8-lane group = 8 x float4 = 128 B = one cache line.

__global__ __launch_bounds__(256) void deform_attn_kernel_v2(
    const float* __restrict__ value,
    const float* __restrict__ loc,
    const float* __restrict__ aw,
    float* __restrict__ out)
{
    const int gtid = blockIdx.x * blockDim.x + threadIdx.x;
    const int warp = gtid >> 5;                 // 0 .. BS*NQ*2 - 1
    const int lane = gtid & 31;
    if (warp >= BS * NQ * (NH / 4)) return;

    const int g   = lane >> 3;                  // head within group: 0..3
    const int sub = lane & 7;                   // float4 slot within head: 0..7

    const int hg  = warp & 1;                   // head-group: 0 or 1
    const int bq  = warp >> 1;                  // b*NQ + q
    const int b   = bq / NQ;
    const int head = hg * 4 + g;

    // value base for this (b, head, sub), in float4 units; pixel stride = 64 float4
    const float4* __restrict__ vbase =
        reinterpret_cast<const float4*>(value) +
        (size_t)b * (SH * SW * (NH * HD / 4)) + head * (HD / 4) + sub;

    const int lq_base = (bq * NH + head) * NP;
    const float2* __restrict__ lptr = reinterpret_cast<const float2*>(loc) + lq_base;
    const float*  __restrict__ wptr = aw + lq_base;

    float4 accA = make_float4(0.f, 0.f, 0.f, 0.f);
    float4 accB = make_float4(0.f, 0.f, 0.f, 0.f);

#pragma unroll
    for (int p = 0; p < NP; ++p) {
        const float2 l = __ldg(lptr + p);
        const float  w = __ldg(wptr + p);

        // grid = 2*loc - 1; unnormalize (align_corners=False): x = loc.x*W - 0.5
        const float x = l.x * (float)SW - 0.5f;
        const float y = l.y * (float)SH - 0.5f;

        const float xf = floorf(x);
        const float yf = floorf(y);
        const int x0 = (int)xf;
        const int y0 = (int)yf;
        const int x1 = x0 + 1;
        const int y1 = y0 + 1;
        const float tx = x - xf;
        const float ty = y - yf;

        // validity folded into weights (branchless)
        const float vx0 = (x0 >= 0 && x0 < SW) ? 1.f : 0.f;
        const float vx1 = (x1 >= 0 && x1 < SW) ? 1.f : 0.f;
        const float vy0 = (y0 >= 0 && y0 < SH) ? 1.f : 0.f;
        const float vy1 = (y1 >= 0 && y1 < SH) ? 1.f : 0.f;

        const int xc0 = min(max(x0, 0), SW - 1);
        const int xc1 = min(max(x1, 0), SW - 1);
        const int yc0 = min(max(y0, 0), SH - 1);
        const int yc1 = min(max(y1, 0), SH - 1);

        const float w00 = (1.f - tx) * (1.f - ty) * vx0 * vy0 * w;
        const float w10 = tx * (1.f - ty) * vx1 * vy0 * w;
        const float w01 = (1.f - tx) * ty * vx0 * vy1 * w;
        const float w11 = tx * ty * vx1 * vy1 * w;

        const int r0 = yc0 * SW;
        const int r1 = yc1 * SW;

        // 4 corner loads (independent -> MLP)
        const float4 v00 = __ldg(vbase + (size_t)(r0 + xc0) * 64);
        const float4 v10 = __ldg(vbase + (size_t)(r0 + xc1) * 64);
        const float4 v01 = __ldg(vbase + (size_t)(r1 + xc0) * 64);
        const float4 v11 = __ldg(vbase + (size_t)(r1 + xc1) * 64);

        accA.x = fmaf(w00, v00.x, accA.x); accA.y = fmaf(w00, v00.y, accA.y);
        accA.z = fmaf(w00, v00.z, accA.z); accA.w = fmaf(w00, v00.w, accA.w);
        accB.x = fmaf(w10, v10.x, accB.x); accB.y = fmaf(w10, v10.y, accB.y);
        accB.z = fmaf(w10, v10.z, accB.z); accB.w = fmaf(w10, v10.w, accB.w);
        accA.x = fmaf(w01, v01.x, accA.x); accA.y = fmaf(w01, v01.y, accA.y);
        accA.z = fmaf(w01, v01.z, accA.z); accA.w = fmaf(w01, v01.w, accA.w);
        accB.x = fmaf(w11, v11.x, accB.x); accB.y = fmaf(w11, v11.y, accB.y);
        accB.z = fmaf(w11, v11.z, accB.z); accB.w = fmaf(w11, v11.w, accB.w);
    }

    float4 acc;
    acc.x = accA.x + accB.x;
    acc.y = accA.y + accB.y;
    acc.z = accA.z + accB.z;
    acc.w = accA.w + accB.w;

    // out: (b, q, head*32 + sub*4) -> float4 index bq*64 + head*8 + sub (contiguous per warp)
    float4* __restrict__ optr =
        reinterpret_cast<float4*>(out) + (size_t)bq * (NH * HD / 4) + head * (HD / 4) + sub;
    *optr = acc;
}

extern "C" void kernel_launch(void* const* d_in, const int* in_sizes, int n_in,
                              void* d_out, int out_size)
{
    const float* value = (const float*)d_in[0];
    // d_in[1] = value_spatial_shapes (int64), unused in fixed-size variant
    const float* loc = (const float*)d_in[2];
    const float* aw = (const float*)d_in[3];
    float* out = (float*)d_out;

    const int total_warps = BS * NQ * (NH / 4);      // 80000
    const int threads = 256;                          // 8 warps per block
    const int blocks = (total_warps * 32 + threads - 1) / threads;  // 10000

    deform_attn_kernel_v2<<<blocks, threads>>>(value, loc, aw, out);
}

// round 7
// speedup vs baseline: 2.3743x; 1.0260x over previous
#include <cuda_runtime.h>
#include <cstdint>

// Problem constants (fixed-shape variant)
#define BS 4
#define NQ 10000
#define NH 8
#define HD 32
#define NP 4
#define SH 100
#define SW 100

// value layout: [b][pix][h][d], pix = y*SW + x   (pixel stride = NH*HD = 256 floats = 64 float4)
// loc layout:   [b][q][h][0][p][2]
// aw layout:    [b][q][h][0][p]
// out layout:   [b][q][h*HD + d]
//
// One warp handles (b, q, head-group hg) where hg selects 4 heads.
// lane: g = lane>>3 -> head = hg*4+g ; sub = lane&7 -> channels [sub*4, sub*4+4)
// Each corner gather per 8-lane group = 8 x float4 = 128 B = one cache line.

__global__ __launch_bounds__(256) void deform_attn_kernel_v2(
    const float* __restrict__ value,
    const float* __restrict__ loc,
    const float* __restrict__ aw,
    float* __restrict__ out)
{
    const int gtid = blockIdx.x * blockDim.x + threadIdx.x;
    const int warp = gtid >> 5;                 // 0 .. BS*NQ*2 - 1
    const int lane = gtid & 31;
    if (warp >= BS * NQ * (NH / 4)) return;

    const int g   = lane >> 3;                  // head within group: 0..3
    const int sub = lane & 7;                   // float4 slot within head: 0..7

    const int hg  = warp & 1;                   // head-group: 0 or 1
    const int bq  = warp >> 1;                  // b*NQ + q
    const int b   = bq / NQ;
    const int head = hg * 4 + g;

    // value base for this (b, head, sub), in float4 units; pixel stride = 64 float4
    const float4* __restrict__ vbase =
        reinterpret_cast<const float4*>(value) +
        (size_t)b * (SH * SW * (NH * HD / 4)) + head * (HD / 4) + sub;

    const int lq_base = (bq * NH + head) * NP;
    const float2* __restrict__ lptr = reinterpret_cast<const float2*>(loc) + lq_base;
    const float*  __restrict__ wptr = aw + lq_base;

    float4 accA = make_float4(0.f, 0.f, 0.f, 0.f);
    float4 accB = make_float4(0.f, 0.f, 0.f, 0.f);

#pragma unroll
    for (int p = 0; p < NP; ++p) {
        const float2 l = __ldg(lptr + p);
        const float  w = __ldg(wptr + p);

        // grid = 2*loc - 1; unnormalize (align_corners=False): x = loc.x*W - 0.5
        const float x = l.x * (float)SW - 0.5f;
        const float y = l.y * (float)SH - 0.5f;

        const float xf = floorf(x);
        const float yf = floorf(y);
        const int x0 = (int)xf;
        const int y0 = (int)yf;
        const int x1 = x0 + 1;
        const int y1 = y0 + 1;
        const float tx = x - xf;
        const float ty = y - yf;

        // validity folded into weights (branchless)
        const float vx0 = (x0 >= 0 && x0 < SW) ? 1.f : 0.f;
        const float vx1 = (x1 >= 0 && x1 < SW) ? 1.f : 0.f;
        const float vy0 = (y0 >= 0 && y0 < SH) ? 1.f : 0.f;
        const float vy1 = (y1 >= 0 && y1 < SH) ? 1.f : 0.f;

        const int xc0 = min(max(x0, 0), SW - 1);
        const int xc1 = min(max(x1, 0), SW - 1);
        const int yc0 = min(max(y0, 0), SH - 1);
        const int yc1 = min(max(y1, 0), SH - 1);

        const float w00 = (1.f - tx) * (1.f - ty) * vx0 * vy0 * w;
        const float w10 = tx * (1.f - ty) * vx1 * vy0 * w;
        const float w01 = (1.f - tx) * ty * vx0 * vy1 * w;
        const float w11 = tx * ty * vx1 * vy1 * w;

        const int r0 = yc0 * SW;
        const int r1 = yc1 * SW;

        // 4 corner loads (independent -> MLP)
        const float4 v00 = __ldg(vbase + (size_t)(r0 + xc0) * 64);
        const float4 v10 = __ldg(vbase + (size_t)(r0 + xc1) * 64);
        const float4 v01 = __ldg(vbase + (size_t)(r1 + xc0) * 64);
        const float4 v11 = __ldg(vbase + (size_t)(r1 + xc1) * 64);

        accA.x = fmaf(w00, v00.x, accA.x); accA.y = fmaf(w00, v00.y, accA.y);
        accA.z = fmaf(w00, v00.z, accA.z); accA.w = fmaf(w00, v00.w, accA.w);
        accB.x = fmaf(w10, v10.x, accB.x); accB.y = fmaf(w10, v10.y, accB.y);
        accB.z = fmaf(w10, v10.z, accB.z); accB.w = fmaf(w10, v10.w, accB.w);
        accA.x = fmaf(w01, v01.x, accA.x); accA.y = fmaf(w01, v01.y, accA.y);
        accA.z = fmaf(w01, v01.z, accA.z); accA.w = fmaf(w01, v01.w, accA.w);
        accB.x = fmaf(w11, v11.x, accB.x); accB.y = fmaf(w11, v11.y, accB.y);
        accB.z = fmaf(w11, v11.z, accB.z); accB.w = fmaf(w11, v11.w, accB.w);
    }

    float4 acc;
    acc.x = accA.x + accB.x;
    acc.y = accA.y + accB.y;
    acc.z = accA.z + accB.z;
    acc.w = accA.w + accB.w;

    // out: (b, q, head*32 + sub*4) -> float4 index bq*64 + head*8 + sub (contiguous per warp)
    float4* __restrict__ optr =
        reinterpret_cast<float4*>(out) + (size_t)bq * (NH * HD / 4) + head * (HD / 4) + sub;
    *optr = acc;
}

extern "C" void kernel_launch(void* const* d_in, const int* in_sizes, int n_in,
                              void* d_out, int out_size)
{
    const float* value = (const float*)d_in[0];
    // d_in[1] = value_spatial_shapes (int64), unused in fixed-size variant
    const float* loc = (const float*)d_in[2];
    const float* aw = (const float*)d_in[3];
    float* out = (float*)d_out;

    const int total_warps = BS * NQ * (NH / 4);      // 80000
    const int threads = 256;                          // 8 warps per block
    const int blocks = (total_warps * 32 + threads - 1) / threads;  // 10000

    deform_attn_kernel_v2<<<blocks, threads>>>(value, loc, aw, out);
}